// round 2
// baseline (speedup 1.0000x reference)
#include <cuda_runtime.h>
#include <math.h>

// Problem constants (fixed by the reference)
constexpr int Bsz = 32;
constexpr int Lsz = 2048;
constexpr int Hsz = 1024;

// Scratch (device-global: no allocations allowed)
__device__ float g_wq[Bsz * Hsz];        // wa(query) + wa_b, per batch
__device__ float g_scores[Bsz * Lsz];    // pre-softmax scores
__device__ float g_weights[Bsz * Lsz];   // softmax weights
__device__ float g_part[8][Bsz * Hsz];   // partial contexts (L split 8 ways)

// ---------------------------------------------------------------------------
// Kernel A: wq[b,k] = sum_h query[b,h] * wa_w[k,h] + wa_b[k]
// One block per b; warp per output row, coalesced float4 row reads.
// ---------------------------------------------------------------------------
__global__ __launch_bounds__(256) void wq_kernel(
    const float* __restrict__ query,
    const float* __restrict__ wa_w,
    const float* __restrict__ wa_b)
{
    __shared__ __align__(16) float qs[Hsz];
    const int b = blockIdx.x;
    for (int i = threadIdx.x; i < Hsz / 4; i += blockDim.x)
        ((float4*)qs)[i] = ((const float4*)(query + (size_t)b * Hsz))[i];
    __syncthreads();

    const int warp = threadIdx.x >> 5;
    const int lane = threadIdx.x & 31;
    for (int k = warp; k < Hsz; k += 8) {
        const float4* wrow = (const float4*)(wa_w + (size_t)k * Hsz);
        float sum = 0.f;
        #pragma unroll
        for (int i = 0; i < 8; i++) {
            float4 wv = wrow[lane + 32 * i];
            float4 qv = ((const float4*)qs)[lane + 32 * i];
            sum += wv.x * qv.x + wv.y * qv.y + wv.z * qv.z + wv.w * qv.w;
        }
        #pragma unroll
        for (int off = 16; off; off >>= 1)
            sum += __shfl_down_sync(0xffffffffu, sum, off);
        if (lane == 0) g_wq[b * Hsz + k] = sum + wa_b[k];
    }
}

// ---------------------------------------------------------------------------
// Kernel B: fused  scores[b,l] = va_b + sum_k va_w[k] *
//                    tanh( wq[b,k] + ua_b[k] + sum_h keys[b,l,h]*ua_w[k,h] )
// Tiled GEMM (M=128 rows of l, N=64 cols of k per pass, K=h in chunks of 32)
// with the tanh/va epilogue fused so uk never hits global memory.
// ---------------------------------------------------------------------------
constexpr int TL = 128;  // l-rows per block
constexpr int TK = 64;   // k-cols per pass
constexpr int KH = 32;   // h-chunk

__global__ __launch_bounds__(256) void scores_kernel(
    const float* __restrict__ keys,
    const float* __restrict__ ua_w,
    const float* __restrict__ ua_b,
    const float* __restrict__ va_w,
    const float* __restrict__ va_b,
    const unsigned char* __restrict__ mask)
{
    __shared__ __align__(16) float sA[KH][TL + 4];  // keys^T tile: sA[h][l]
    __shared__ __align__(16) float sB[KH][TK + 4];  // ua_w^T tile: sB[h][k]

    const int b  = blockIdx.y;
    const int l0 = blockIdx.x * TL;
    const int tid = threadIdx.x;
    const int ty = tid >> 4;   // 0..15 -> 8 l-rows each
    const int tx = tid & 15;   // 0..15 -> 4 k-cols each

    const float* keysB = keys + ((size_t)b * Lsz + l0) * Hsz;

    float scoreAcc[8];
    #pragma unroll
    for (int i = 0; i < 8; i++) scoreAcc[i] = 0.f;

    for (int kt = 0; kt < Hsz / TK; kt++) {
        float acc[8][4];
        #pragma unroll
        for (int i = 0; i < 8; i++)
            #pragma unroll
            for (int j = 0; j < 4; j++) acc[i][j] = 0.f;

        for (int ht = 0; ht < Hsz / KH; ht++) {
            // Load keys tile (128 x 32), transposed into sA[h][l]
            {
                const int r  = tid >> 3;   // 0..31
                const int c4 = tid & 7;    // 0..7  (float4 column)
                #pragma unroll
                for (int p = 0; p < 4; p++) {
                    const int row = r + p * 32;
                    float4 v = *(const float4*)(keysB + (size_t)row * Hsz + ht * KH + c4 * 4);
                    sA[c4 * 4 + 0][row] = v.x;
                    sA[c4 * 4 + 1][row] = v.y;
                    sA[c4 * 4 + 2][row] = v.z;
                    sA[c4 * 4 + 3][row] = v.w;
                }
                // Load ua_w tile (64 x 32), transposed into sB[h][k]
                #pragma unroll
                for (int p = 0; p < 2; p++) {
                    const int row = r + p * 32;
                    float4 v = *(const float4*)(ua_w + (size_t)(kt * TK + row) * Hsz + ht * KH + c4 * 4);
                    sB[c4 * 4 + 0][row] = v.x;
                    sB[c4 * 4 + 1][row] = v.y;
                    sB[c4 * 4 + 2][row] = v.z;
                    sB[c4 * 4 + 3][row] = v.w;
                }
            }
            __syncthreads();

            #pragma unroll
            for (int kk = 0; kk < KH; kk++) {
                float4 a0 = *(const float4*)&sA[kk][ty * 8];
                float4 a1 = *(const float4*)&sA[kk][ty * 8 + 4];
                float4 bv = *(const float4*)&sB[kk][tx * 4];
                const float a[8] = {a0.x, a0.y, a0.z, a0.w, a1.x, a1.y, a1.z, a1.w};
                const float bb[4] = {bv.x, bv.y, bv.z, bv.w};
                #pragma unroll
                for (int i = 0; i < 8; i++)
                    #pragma unroll
                    for (int j = 0; j < 4; j++)
                        acc[i][j] += a[i] * bb[j];
            }
            __syncthreads();
        }

        // Fused epilogue: tanh + va-weighted reduction over this k-slab
        float part[8];
        #pragma unroll
        for (int i = 0; i < 8; i++) part[i] = 0.f;
        #pragma unroll
        for (int j = 0; j < 4; j++) {
            const int k = kt * TK + tx * 4 + j;
            const float wqv = g_wq[b * Hsz + k] + ua_b[k];
            const float vw  = va_w[k];
            #pragma unroll
            for (int i = 0; i < 8; i++)
                part[i] += vw * tanhf(acc[i][j] + wqv);
        }
        // Reduce over the 16 tx lanes (segmented shuffle, width 16)
        #pragma unroll
        for (int i = 0; i < 8; i++) {
            float v = part[i];
            #pragma unroll
            for (int off = 8; off; off >>= 1)
                v += __shfl_down_sync(0xffffffffu, v, off, 16);
            if (tx == 0) scoreAcc[i] += v;
        }
    }

    if (tx == 0) {
        const float vb = va_b[0];
        #pragma unroll
        for (int i = 0; i < 8; i++) {
            const int l = l0 + ty * 8 + i;
            float s = scoreAcc[i] + vb;
            if (mask[b * Lsz + l]) s = -INFINITY;
            g_scores[b * Lsz + l] = s;
        }
    }
}

// ---------------------------------------------------------------------------
// Kernel C: softmax over L per batch
// ---------------------------------------------------------------------------
__global__ __launch_bounds__(256) void softmax_kernel()
{
    __shared__ float red[256];
    const int b = blockIdx.x;
    const int tid = threadIdx.x;

    float mx = -INFINITY;
    for (int l = tid; l < Lsz; l += 256) mx = fmaxf(mx, g_scores[b * Lsz + l]);
    red[tid] = mx;
    __syncthreads();
    for (int s = 128; s; s >>= 1) {
        if (tid < s) red[tid] = fmaxf(red[tid], red[tid + s]);
        __syncthreads();
    }
    mx = red[0];
    __syncthreads();

    float sum = 0.f;
    for (int l = tid; l < Lsz; l += 256) {
        const float e = expf(g_scores[b * Lsz + l] - mx);
        g_weights[b * Lsz + l] = e;
        sum += e;
    }
    red[tid] = sum;
    __syncthreads();
    for (int s = 128; s; s >>= 1) {
        if (tid < s) red[tid] += red[tid + s];
        __syncthreads();
    }
    const float inv = 1.f / red[0];
    for (int l = tid; l < Lsz; l += 256) g_weights[b * Lsz + l] *= inv;
}

// ---------------------------------------------------------------------------
// Kernel D: partial contexts — block (lsplit, b), each thread 4 h-values
// ---------------------------------------------------------------------------
__global__ __launch_bounds__(256) void context_kernel(const float* __restrict__ keys)
{
    __shared__ float wsh[256];
    const int s = blockIdx.x;  // 0..7
    const int b = blockIdx.y;
    const int t = threadIdx.x;

    wsh[t] = g_weights[b * Lsz + s * 256 + t];
    __syncthreads();

    float4 acc = make_float4(0.f, 0.f, 0.f, 0.f);
    const float* kb = keys + ((size_t)b * Lsz + s * 256) * Hsz;
    #pragma unroll 4
    for (int l = 0; l < 256; l++) {
        const float w = wsh[l];
        float4 kv = *(const float4*)(kb + (size_t)l * Hsz + t * 4);
        acc.x += w * kv.x;
        acc.y += w * kv.y;
        acc.z += w * kv.z;
        acc.w += w * kv.w;
    }
    *(float4*)&g_part[s][b * Hsz + t * 4] = acc;
}

// ---------------------------------------------------------------------------
// Kernel E: reduce the 8 partials into d_out
// ---------------------------------------------------------------------------
__global__ __launch_bounds__(256) void reduce_kernel(float* __restrict__ out)
{
    const int i = blockIdx.x * 256 + threadIdx.x;  // < Bsz*Hsz
    float s = 0.f;
    #pragma unroll
    for (int p = 0; p < 8; p++) s += g_part[p][i];
    out[i] = s;
}

// ---------------------------------------------------------------------------
extern "C" void kernel_launch(void* const* d_in, const int* in_sizes, int n_in,
                              void* d_out, int out_size)
{
    const float* query = (const float*)d_in[0];
    const float* keys  = (const float*)d_in[1];
    const unsigned char* mask = (const unsigned char*)d_in[2];
    const float* wa_w = (const float*)d_in[3];
    const float* wa_b = (const float*)d_in[4];
    const float* ua_w = (const float*)d_in[5];
    const float* ua_b = (const float*)d_in[6];
    const float* va_w = (const float*)d_in[7];
    const float* va_b = (const float*)d_in[8];
    float* out = (float*)d_out;

    wq_kernel<<<Bsz, 256>>>(query, wa_w, wa_b);
    scores_kernel<<<dim3(Lsz / TL, Bsz), 256>>>(keys, ua_w, ua_b, va_w, va_b, mask);
    softmax_kernel<<<Bsz, 256>>>();
    context_kernel<<<dim3(8, Bsz), 256>>>(keys);
    reduce_kernel<<<(Bsz * Hsz) / 256, 256>>>(out);
}

// round 6
// speedup vs baseline: 2.6011x; 2.6011x over previous
#include <cuda_runtime.h>
#include <cuda_bf16.h>
#include <math.h>
#include <stdint.h>

// Problem constants
constexpr int Bsz = 32;
constexpr int Lsz = 2048;
constexpr int Hsz = 1024;

// Scratch
__device__ float g_wq[Bsz * Hsz];
__device__ float g_scores[Bsz * Lsz];
__device__ float g_weights[Bsz * Lsz];
__device__ float g_part[8][Bsz * Hsz];

// ---------------------------------------------------------------------------
// mma.sync / ldmatrix helpers (sm_80+ baseline features, valid on sm_100)
// ---------------------------------------------------------------------------
__device__ __forceinline__ uint32_t smem_to_u32(const void* p) {
    uint32_t a;
    asm("{ .reg .u64 t; cvta.to.shared.u64 t, %1; cvt.u32.u64 %0, t; }" : "=r"(a) : "l"(p));
    return a;
}

__device__ __forceinline__ void ldsm_x4(uint32_t* r, uint32_t addr) {
    asm volatile("ldmatrix.sync.aligned.m8n8.x4.shared.b16 {%0,%1,%2,%3}, [%4];"
        : "=r"(r[0]), "=r"(r[1]), "=r"(r[2]), "=r"(r[3]) : "r"(addr));
}
__device__ __forceinline__ void ldsm_x2(uint32_t* r, uint32_t addr) {
    asm volatile("ldmatrix.sync.aligned.m8n8.x2.shared.b16 {%0,%1}, [%2];"
        : "=r"(r[0]), "=r"(r[1]) : "r"(addr));
}
__device__ __forceinline__ void mma_bf16(float* c, const uint32_t* a, const uint32_t* b) {
    asm volatile("mma.sync.aligned.m16n8k16.row.col.f32.bf16.bf16.f32 "
        "{%0,%1,%2,%3}, {%4,%5,%6,%7}, {%8,%9}, {%0,%1,%2,%3};"
        : "+f"(c[0]), "+f"(c[1]), "+f"(c[2]), "+f"(c[3])
        : "r"(a[0]), "r"(a[1]), "r"(a[2]), "r"(a[3]), "r"(b[0]), "r"(b[1]));
}

// ---------------------------------------------------------------------------
// Kernel A: wq[b,k] = query[b,:]·wa_w[k,:] + wa_b[k]
// ---------------------------------------------------------------------------
__global__ __launch_bounds__(256) void wq_kernel(
    const float* __restrict__ query, const float* __restrict__ wa_w,
    const float* __restrict__ wa_b)
{
    __shared__ __align__(16) float qs[Hsz];
    const int b = blockIdx.x;
    for (int i = threadIdx.x; i < Hsz / 4; i += blockDim.x)
        ((float4*)qs)[i] = ((const float4*)(query + (size_t)b * Hsz))[i];
    __syncthreads();

    const int warp = threadIdx.x >> 5;
    const int lane = threadIdx.x & 31;
    for (int k = warp; k < Hsz; k += 8) {
        const float4* wrow = (const float4*)(wa_w + (size_t)k * Hsz);
        float sum = 0.f;
        #pragma unroll
        for (int i = 0; i < 8; i++) {
            float4 wv = wrow[lane + 32 * i];
            float4 qv = ((const float4*)qs)[lane + 32 * i];
            sum += wv.x * qv.x + wv.y * qv.y + wv.z * qv.z + wv.w * qv.w;
        }
        #pragma unroll
        for (int off = 16; off; off >>= 1)
            sum += __shfl_down_sync(0xffffffffu, sum, off);
        if (lane == 0) g_wq[b * Hsz + k] = sum + wa_b[k];
    }
}

// ---------------------------------------------------------------------------
// Kernel B: fused scores via bf16x3 mma.sync.
// CTA = 128 l-rows x all 1024 k. 8 warps: warp w owns l-rows [w*16, w*16+16).
// kc: 4 passes of KC=256 k (warp tile M16 x N256 -> 128 fp32 accums/lane).
// h streamed in HC=32 chunks, double-buffered SMEM, reg-prefetch of globals.
// ---------------------------------------------------------------------------
constexpr int TM = 128;
constexpr int KC = 256;
constexpr int HC = 32;
constexpr int NHC = Hsz / HC;   // 32
constexpr int ROWB = 80;        // smem row stride: 64B data + 16B pad (no ldsm conflicts)

constexpr int SM_C   = 0;                     // wq+ua_b: 4KB
constexpr int SM_VA  = 4096;                  // va_w:    4KB
constexpr int SM_A   = 8192;                  // A bufs: [buf][hi/lo][128*80]
constexpr int A_BUF  = TM * ROWB;             // 10240
constexpr int SM_B   = SM_A + 4 * A_BUF;      // 49152; B bufs: [buf][hi/lo][256*80]
constexpr int B_BUF  = KC * ROWB;             // 20480
constexpr int SM_TOTAL = SM_B + 4 * B_BUF;    // 131072

__device__ __forceinline__ void store_split(char* hi, char* lo, int off, float4 v) {
    __nv_bfloat16 h0 = __float2bfloat16_rn(v.x);
    __nv_bfloat16 h1 = __float2bfloat16_rn(v.y);
    __nv_bfloat16 h2 = __float2bfloat16_rn(v.z);
    __nv_bfloat16 h3 = __float2bfloat16_rn(v.w);
    __nv_bfloat16 l0 = __float2bfloat16_rn(v.x - __bfloat162float(h0));
    __nv_bfloat16 l1 = __float2bfloat16_rn(v.y - __bfloat162float(h1));
    __nv_bfloat16 l2 = __float2bfloat16_rn(v.z - __bfloat162float(h2));
    __nv_bfloat16 l3 = __float2bfloat16_rn(v.w - __bfloat162float(h3));
    __nv_bfloat162 ha = __halves2bfloat162(h0, h1), hb = __halves2bfloat162(h2, h3);
    __nv_bfloat162 la = __halves2bfloat162(l0, l1), lb = __halves2bfloat162(l2, l3);
    *reinterpret_cast<uint2*>(hi + off) =
        make_uint2(*reinterpret_cast<uint32_t*>(&ha), *reinterpret_cast<uint32_t*>(&hb));
    *reinterpret_cast<uint2*>(lo + off) =
        make_uint2(*reinterpret_cast<uint32_t*>(&la), *reinterpret_cast<uint32_t*>(&lb));
}

__global__ __launch_bounds__(256, 1) void scores_mma_kernel(
    const float* __restrict__ keys,
    const float* __restrict__ ua_w,
    const float* __restrict__ ua_b,
    const float* __restrict__ va_w,
    const float* __restrict__ va_b,
    const unsigned char* __restrict__ mask)
{
    extern __shared__ __align__(128) char smem[];
    const uint32_t sbase = smem_to_u32(smem);
    const int tid  = threadIdx.x;
    const int lane = tid & 31;
    const int w    = tid >> 5;
    const int b    = blockIdx.y;
    const int l0   = blockIdx.x * TM;

    float* s_c  = (float*)(smem + SM_C);
    float* s_va = (float*)(smem + SM_VA);
    for (int i = tid; i < Hsz; i += 256) {
        s_c[i]  = g_wq[b * Hsz + i] + ua_b[i];
        s_va[i] = va_w[i];
    }

    const float* keysB = keys + ((size_t)b * Lsz + l0) * Hsz;

    float sc0 = 0.f, sc1 = 0.f;

    // ldmatrix fixed per-lane address components
    const int arow = w * 16 + (lane & 15);       // A row for this lane's tile slot
    const int aco  = (lane >> 4) << 4;           // +0 or +16 bytes (k half)
    const int brow = lane & 7;                   // B n-row within subtile
    const int bco  = ((lane >> 3) & 1) << 4;     // +0 or +16 bytes (k half)

    #pragma unroll 1
    for (int kc = 0; kc < 4; kc++) {
        float acc[32][4];
        #pragma unroll
        for (int nt = 0; nt < 32; nt++)
            #pragma unroll
            for (int j = 0; j < 4; j++) acc[nt][j] = 0.f;

        // ---- prologue: chunk 0 -> buffer 0 ----
        {
            #pragma unroll
            for (int p = 0; p < 4; p++) {
                int idx = p * 256 + tid;
                float4 v = *(const float4*)(keysB + (size_t)(idx >> 3) * Hsz + (idx & 7) * 4);
                store_split(smem + SM_A, smem + SM_A + A_BUF,
                            (idx >> 3) * ROWB + (idx & 7) * 8, v);
            }
            #pragma unroll
            for (int p = 0; p < 8; p++) {
                int idx = p * 256 + tid;
                float4 v = *(const float4*)(ua_w + (size_t)(kc * KC + (idx >> 3)) * Hsz + (idx & 7) * 4);
                store_split(smem + SM_B, smem + SM_B + B_BUF,
                            (idx >> 3) * ROWB + (idx & 7) * 8, v);
            }
        }
        __syncthreads();

        #pragma unroll 1
        for (int hc = 0; hc < NHC; hc++) {
            const int cur = hc & 1, nxt = cur ^ 1;
            const bool pf = (hc + 1 < NHC);

            // ---- prefetch next chunk (global -> regs), issued before MMA ----
            float4 ra[4], rb[8];
            if (pf) {
                const int h0 = (hc + 1) * HC;
                #pragma unroll
                for (int p = 0; p < 4; p++) {
                    int idx = p * 256 + tid;
                    ra[p] = *(const float4*)(keysB + (size_t)(idx >> 3) * Hsz + h0 + (idx & 7) * 4);
                }
                #pragma unroll
                for (int p = 0; p < 8; p++) {
                    int idx = p * 256 + tid;
                    rb[p] = *(const float4*)(ua_w + (size_t)(kc * KC + (idx >> 3)) * Hsz + h0 + (idx & 7) * 4);
                }
            }

            // ---- MMA block on current buffer ----
            const uint32_t a_hi = sbase + SM_A + cur * (2 * A_BUF);
            const uint32_t a_lo = a_hi + A_BUF;
            const uint32_t b_hi = sbase + SM_B + cur * (2 * B_BUF);
            const uint32_t b_lo = b_hi + B_BUF;

            #pragma unroll
            for (int ks = 0; ks < 2; ks++) {
                uint32_t ah[4], al[4];
                ldsm_x4(ah, a_hi + arow * ROWB + ks * 32 + aco);
                ldsm_x4(al, a_lo + arow * ROWB + ks * 32 + aco);
                const uint32_t bh0 = b_hi + brow * ROWB + ks * 32 + bco;
                const uint32_t bl0 = b_lo + brow * ROWB + ks * 32 + bco;
                #pragma unroll
                for (int nt = 0; nt < 32; nt++) {
                    uint32_t bh[2], bl[2];
                    ldsm_x2(bh, bh0 + nt * 8 * ROWB);
                    ldsm_x2(bl, bl0 + nt * 8 * ROWB);
                    mma_bf16(acc[nt], ah, bh);
                    mma_bf16(acc[nt], ah, bl);
                    mma_bf16(acc[nt], al, bh);
                }
            }

            // ---- store prefetched chunk into the other buffer ----
            if (pf) {
                char* Ah = smem + SM_A + nxt * (2 * A_BUF);
                char* Bh = smem + SM_B + nxt * (2 * B_BUF);
                #pragma unroll
                for (int p = 0; p < 4; p++) {
                    int idx = p * 256 + tid;
                    store_split(Ah, Ah + A_BUF, (idx >> 3) * ROWB + (idx & 7) * 8, ra[p]);
                }
                #pragma unroll
                for (int p = 0; p < 8; p++) {
                    int idx = p * 256 + tid;
                    store_split(Bh, Bh + B_BUF, (idx >> 3) * ROWB + (idx & 7) * 8, rb[p]);
                }
            }
            __syncthreads();
        }

        // ---- epilogue: tanh + va-weighted reduction over this kc's 256 cols ----
        float p0 = 0.f, p1 = 0.f;
        #pragma unroll
        for (int nt = 0; nt < 32; nt++) {
            const int col = nt * 8 + (lane & 3) * 2;
            const int k = kc * KC + col;
            const float c0 = s_c[k], c1 = s_c[k + 1];
            const float v0 = s_va[k], v1 = s_va[k + 1];
            p0 += v0 * tanhf(acc[nt][0] + c0);
            p0 += v1 * tanhf(acc[nt][1] + c1);
            p1 += v0 * tanhf(acc[nt][2] + c0);
            p1 += v1 * tanhf(acc[nt][3] + c1);
        }
        p0 += __shfl_xor_sync(0xffffffffu, p0, 1);
        p0 += __shfl_xor_sync(0xffffffffu, p0, 2);
        p1 += __shfl_xor_sync(0xffffffffu, p1, 1);
        p1 += __shfl_xor_sync(0xffffffffu, p1, 2);
        sc0 += p0;
        sc1 += p1;
    }

    // ---- write scores (lane%4==0 lanes hold the reduced row sums) ----
    if ((lane & 3) == 0) {
        const int r = lane >> 2;
        int l = l0 + w * 16 + r;
        float s = sc0 + va_b[0];
        if (mask[b * Lsz + l]) s = -INFINITY;
        g_scores[b * Lsz + l] = s;
        l += 8;
        s = sc1 + va_b[0];
        if (mask[b * Lsz + l]) s = -INFINITY;
        g_scores[b * Lsz + l] = s;
    }
}

// ---------------------------------------------------------------------------
// Kernel C: softmax over L per batch
// ---------------------------------------------------------------------------
__global__ __launch_bounds__(256) void softmax_kernel()
{
    __shared__ float red[256];
    const int b = blockIdx.x;
    const int tid = threadIdx.x;

    float mx = -INFINITY;
    for (int l = tid; l < Lsz; l += 256) mx = fmaxf(mx, g_scores[b * Lsz + l]);
    red[tid] = mx;
    __syncthreads();
    for (int s = 128; s; s >>= 1) {
        if (tid < s) red[tid] = fmaxf(red[tid], red[tid + s]);
        __syncthreads();
    }
    mx = red[0];
    __syncthreads();

    float sum = 0.f;
    for (int l = tid; l < Lsz; l += 256) {
        const float e = expf(g_scores[b * Lsz + l] - mx);
        g_weights[b * Lsz + l] = e;
        sum += e;
    }
    red[tid] = sum;
    __syncthreads();
    for (int s = 128; s; s >>= 1) {
        if (tid < s) red[tid] += red[tid + s];
        __syncthreads();
    }
    const float inv = 1.f / red[0];
    for (int l = tid; l < Lsz; l += 256) g_weights[b * Lsz + l] *= inv;
}

// ---------------------------------------------------------------------------
// Kernel D: partial contexts
// ---------------------------------------------------------------------------
__global__ __launch_bounds__(256) void context_kernel(const float* __restrict__ keys)
{
    __shared__ float wsh[256];
    const int s = blockIdx.x;
    const int b = blockIdx.y;
    const int t = threadIdx.x;

    wsh[t] = g_weights[b * Lsz + s * 256 + t];
    __syncthreads();

    float4 acc = make_float4(0.f, 0.f, 0.f, 0.f);
    const float* kb = keys + ((size_t)b * Lsz + s * 256) * Hsz;
    #pragma unroll 4
    for (int l = 0; l < 256; l++) {
        const float w = wsh[l];
        float4 kv = *(const float4*)(kb + (size_t)l * Hsz + t * 4);
        acc.x += w * kv.x;
        acc.y += w * kv.y;
        acc.z += w * kv.z;
        acc.w += w * kv.w;
    }
    *(float4*)&g_part[s][b * Hsz + t * 4] = acc;
}

// ---------------------------------------------------------------------------
// Kernel E: reduce partials
// ---------------------------------------------------------------------------
__global__ __launch_bounds__(256) void reduce_kernel(float* __restrict__ out)
{
    const int i = blockIdx.x * 256 + threadIdx.x;
    float s = 0.f;
    #pragma unroll
    for (int p = 0; p < 8; p++) s += g_part[p][i];
    out[i] = s;
}

// ---------------------------------------------------------------------------
extern "C" void kernel_launch(void* const* d_in, const int* in_sizes, int n_in,
                              void* d_out, int out_size)
{
    const float* query = (const float*)d_in[0];
    const float* keys  = (const float*)d_in[1];
    const unsigned char* mask = (const unsigned char*)d_in[2];
    const float* wa_w = (const float*)d_in[3];
    const float* wa_b = (const float*)d_in[4];
    const float* ua_w = (const float*)d_in[5];
    const float* ua_b = (const float*)d_in[6];
    const float* va_w = (const float*)d_in[7];
    const float* va_b = (const float*)d_in[8];
    float* out = (float*)d_out;

    cudaFuncSetAttribute(scores_mma_kernel,
                         cudaFuncAttributeMaxDynamicSharedMemorySize, SM_TOTAL);

    wq_kernel<<<Bsz, 256>>>(query, wa_w, wa_b);
    scores_mma_kernel<<<dim3(Lsz / TM, Bsz), 256, SM_TOTAL>>>(
        keys, ua_w, ua_b, va_w, va_b, mask);
    softmax_kernel<<<Bsz, 256>>>();
    context_kernel<<<dim3(8, Bsz), 256>>>(keys);
    reduce_kernel<<<(Bsz * Hsz) / 256, 256>>>(out);
}